// round 11
// baseline (speedup 1.0000x reference)
#include <cuda_runtime.h>
#include <math.h>
#include <stdint.h>

#define B_DIM 32
#define T_SEQ 512
#define D_DIM 512
#define U_DIM 512
#define NG    2048                 // 4*U
#define M_TOT (B_DIM * T_SEQ)     // 16384

// ---------------- scratch (static device memory; no allocations) ----------------
__device__ float g_xg[2][B_DIM][T_SEQ][NG];        // input projections, both dirs (256 MB)
__device__ float g_hbuf[2][2][B_DIM][U_DIM];       // h double buffers (k-PERMUTED, tf32-rounded)
__device__ float g_hb_out[B_DIM][T_SEQ][U_DIM];    // backward-direction outputs
__device__ float g_xP[M_TOT][D_DIM];               // tf32 x, k-PERMUTED within 8-blocks (32 MB)
__device__ float g_WP[2][NG][D_DIM];               // tf32 W, TRANSPOSED [n][perm k] (16 MB)

// Chunked barrier state (see R8/R9): chunk c = producer CTAs blk 16c..16c+15 = k-range
// [128c,128c+128). Padded lines, monotonic across graph replays.
__device__ unsigned g_chcnt[2][4][32];             // [dir][chunk][pad] arrival counters
__device__ volatile unsigned g_chep[2][4][32];     // [dir][chunk][pad] chunk epochs

#define NCTA_DIR    64
#define REC_THREADS 256

// ---------------- tf32 helpers ----------------
__device__ __forceinline__ unsigned f2tf32(float f)
{
    unsigned r;
    asm("cvt.rna.tf32.f32 %0, %1;" : "=r"(r) : "f"(f));
    return r;
}
__device__ __forceinline__ float tf32f(float f) { return __uint_as_float(f2tf32(f)); }

// D += A@B, m16n8k8, A row-major, B col-major, tf32 in / fp32 accum
__device__ __forceinline__ void mma8(float* c,
                                     unsigned a0, unsigned a1, unsigned a2, unsigned a3,
                                     unsigned b0, unsigned b1)
{
    asm("mma.sync.aligned.m16n8k8.row.col.f32.tf32.tf32.f32 "
        "{%0,%1,%2,%3},{%4,%5,%6,%7},{%8,%9},{%0,%1,%2,%3};"
        : "+f"(c[0]), "+f"(c[1]), "+f"(c[2]), "+f"(c[3])
        : "r"(a0), "r"(a1), "r"(a2), "r"(a3), "r"(b0), "r"(b1));
}

// k-permutation within each 8-block: (pi(k),pi(k)+1) consecutive = (k, k+4)
__device__ __forceinline__ int perm8(int k)
{
    return (k & ~7) | ((k & 3) << 1) | ((k & 7) >> 2);
}

// ---------------- fast transcendentals (MUFU-based, saturation-safe) ----------------
__device__ __forceinline__ float fsigm(float x)
{
    return __fdividef(1.0f, 1.0f + __expf(-x));
}
__device__ __forceinline__ float ftanh(float x)
{
    return 1.0f - __fdividef(2.0f, 1.0f + __expf(2.0f * x));
}

// ---------------- release/acquire barrier primitives (no full MEMBAR) ----------------
__device__ __forceinline__ void ch_arrive(int dir, int chunk, unsigned ep_next)
{
    unsigned v;
    asm volatile("atom.add.release.gpu.u32 %0, [%1], %2;"
                 : "=r"(v)
                 : "l"((unsigned*)&g_chcnt[dir][chunk][0]), "r"(1u)
                 : "memory");
    if ((v & 15u) == 15u)
        asm volatile("st.release.gpu.u32 [%0], %1;"
                     :: "l"((unsigned*)&g_chep[dir][chunk][0]), "r"(ep_next)
                     : "memory");
}

__device__ __forceinline__ void ch_wait(int dir, int ck, unsigned ep0, unsigned need)
{
    unsigned cur;
    do {
        asm volatile("ld.acquire.gpu.u32 %0, [%1];"
                     : "=r"(cur)
                     : "l"((const unsigned*)&g_chep[dir][ck][0])
                     : "memory");
    } while (cur - ep0 < need);
}

// =================================================================================
// Pre-pass 1: g_xP[m][perm8(k)] = tf32(x[m][k])  — pure column permute, no transpose
// =================================================================================
__global__ void cvt_xP(const float* __restrict__ X)
{
    int t = blockIdx.x * blockDim.x + threadIdx.x;   // one 8-block per thread
    if (t < M_TOT * D_DIM / 8) {
        const float* src = X + (size_t)t * 8;
        float4 lo = *(const float4*)src;             // k0..k3
        float4 hi = *(const float4*)(src + 4);       // k4..k7
        float4 o0, o1;                               // positions 0..3, 4..7
        o0.x = tf32f(lo.x); o0.y = tf32f(hi.x); o0.z = tf32f(lo.y); o0.w = tf32f(hi.y);
        o1.x = tf32f(lo.z); o1.y = tf32f(hi.z); o1.z = tf32f(lo.w); o1.w = tf32f(hi.w);
        float* dst = &g_xP[0][0] + (size_t)t * 8;
        *(float4*)dst       = o0;
        *(float4*)(dst + 4) = o1;
    }
}

// =================================================================================
// Pre-pass 2: g_WP[dir][n][perm8(k)] = tf32(W[k][n])  — tiled transpose + permute
// =================================================================================
__global__ void cvt_WP(const float* __restrict__ Wf, const float* __restrict__ Wb)
{
    __shared__ float t[32][33];
    const int dir = blockIdx.z;
    const float* __restrict__ W = dir ? Wb : Wf;
    const int kb = blockIdx.x * 32;
    const int nb = blockIdx.y * 32;
    const int tx = threadIdx.x, ty = threadIdx.y;
    #pragma unroll
    for (int i = ty; i < 32; i += 8)
        t[i][tx] = W[(size_t)(kb + i) * NG + nb + tx];   // t[k'][n']
    __syncthreads();
    const int pk = perm8(tx);                            // permuted k' position
    #pragma unroll
    for (int i = ty; i < 32; i += 8)
        g_WP[dir][nb + i][kb + pk] = tf32f(t[tx][i]);
}

// =================================================================================
// Kernel A: xg[dir] = x @ W[dir] + b[dir]  — tf32 tensor-core GEMM, cp.async ring.
// 128x128 block tile, BK=16, 256 threads. Smem tiles are m/n-MAJOR with k permuted
// (stride 24 floats: conflict-free), so every fragment (k,k+4) pair = one LDS.64:
// 12 LDS.64 per kk-block vs 24 scalar LDS before. Bit-identical numerics.
// =================================================================================
#define AS_STR 24
#define GSMEM  (3 * 128 * AS_STR * 4 * 2)          // As+Bs, 3 buffers = 73,728 B

__global__ __launch_bounds__(256, 2) void gemm_xg(
    const float* __restrict__ bf, const float* __restrict__ bb)
{
    extern __shared__ float gsm[];
    float* As = gsm;                    // [3][128 m][AS_STR]
    float* Bs = gsm + 3 * 128 * AS_STR; // [3][128 n][AS_STR]

    const int dir = blockIdx.z;
    const float* __restrict__ bias = dir ? bb : bf;

    const int tid   = threadIdx.x;
    const int mBase = blockIdx.x * 128;
    const int nBase = blockIdx.y * 128;
    const int lane  = tid & 31, wid = tid >> 5;
    const int gid   = lane >> 2, tig = lane & 3;
    const int m0w   = (wid & 1) * 64;
    const int n0w   = (wid >> 1) * 32;

    const unsigned As_s = (unsigned)__cvta_generic_to_shared(As);
    const unsigned Bs_s = (unsigned)__cvta_generic_to_shared(Bs);

    auto stage = [&](int buf, int kt) {
        #pragma unroll
        for (int j = 0; j < 2; j++) {
            int i   = tid + j * 256;               // 0..511
            int row = i >> 2;                      // 0..127
            int seg = (i & 3) * 4;                 // 0,4,8,12
            const float* srcA = &g_xP[mBase + row][kt + seg];
            const float* srcB = &g_WP[dir][nBase + row][kt + seg];
            unsigned dA = As_s + (unsigned)((buf * 128 + row) * AS_STR + seg) * 4u;
            unsigned dB = Bs_s + (unsigned)((buf * 128 + row) * AS_STR + seg) * 4u;
            asm volatile("cp.async.cg.shared.global [%0], [%1], 16;" :: "r"(dA), "l"(srcA));
            asm volatile("cp.async.cg.shared.global [%0], [%1], 16;" :: "r"(dB), "l"(srcB));
        }
        asm volatile("cp.async.commit_group;");
    };

    float acc[4][4][4];
    #pragma unroll
    for (int i = 0; i < 4; i++)
        #pragma unroll
        for (int j = 0; j < 4; j++)
            #pragma unroll
            for (int q = 0; q < 4; q++) acc[i][j][q] = 0.0f;

    stage(0, 0);
    stage(1, 16);

    int cur = 0;
    for (int kt = 0; kt < D_DIM; kt += 16) {
        if (kt + 32 < D_DIM) asm volatile("cp.async.wait_group 1;");
        else                 asm volatile("cp.async.wait_group 0;");
        __syncthreads();
        if (kt + 32 < D_DIM) stage((cur + 2) % 3, kt + 32);

        const float* Ab = As + cur * 128 * AS_STR;
        const float* Bb = Bs + cur * 128 * AS_STR;
        #pragma unroll
        for (int kk = 0; kk < 16; kk += 8) {
            uint2 aLo[4], aHi[4], bv[4];
            #pragma unroll
            for (int mf = 0; mf < 4; mf++) {
                int mr = m0w + mf * 16 + gid;
                aLo[mf] = *(const uint2*)&Ab[mr * AS_STR + kk + 2 * tig];
                aHi[mf] = *(const uint2*)&Ab[(mr + 8) * AS_STR + kk + 2 * tig];
            }
            #pragma unroll
            for (int nf = 0; nf < 4; nf++) {
                int nr = n0w + nf * 8 + gid;
                bv[nf] = *(const uint2*)&Bb[nr * AS_STR + kk + 2 * tig];
            }
            #pragma unroll
            for (int mf = 0; mf < 4; mf++)
                #pragma unroll
                for (int nf = 0; nf < 4; nf++)
                    mma8(acc[mf][nf], aLo[mf].x, aHi[mf].x, aLo[mf].y, aHi[mf].y,
                         bv[nf].x, bv[nf].y);
        }
        cur = (cur + 1) % 3;
    }

    float* outp = &g_xg[dir][0][0][0];
    #pragma unroll
    for (int nf = 0; nf < 4; nf++) {
        int ncol = nBase + n0w + nf * 8 + 2 * tig;
        float2 bvv = *(const float2*)&bias[ncol];
        #pragma unroll
        for (int mf = 0; mf < 4; mf++) {
            int r0 = mBase + m0w + mf * 16 + gid;
            float2 v0 = make_float2(acc[mf][nf][0] + bvv.x, acc[mf][nf][1] + bvv.y);
            float2 v1 = make_float2(acc[mf][nf][2] + bvv.x, acc[mf][nf][3] + bvv.y);
            *(float2*)(outp + (size_t)r0 * NG + ncol)       = v0;
            *(float2*)(outp + (size_t)(r0 + 8) * NG + ncol) = v1;
        }
    }
}

// =================================================================================
// Kernel B: persistent bidirectional LSTM recurrence — tf32 tensor cores.
// 128 CTAs (64/dir, dir=bid&1), 256 threads, CTA owns 8 units; chunk-wise
// release/acquire barrier. NEW: each khalf's two chunks are polled+staged by
// INDEPENDENT 64-thread sub-groups in parallel (no serial second poll), joined by
// one 128-thread barrier before a straight 32-kb mma run.
// =================================================================================
#define US_STR 520
#define GP_STR 34
#define SMEM_REC ((2 * 32 * US_STR + 2 * 32 * GP_STR) * 4)

__global__ __launch_bounds__(REC_THREADS, 1) void lstm_rec(
    const float* __restrict__ z,
    const float* __restrict__ Uf, const float* __restrict__ Ub,
    float* __restrict__ out)
{
    extern __shared__ float sm[];
    float* Us = sm;                       // [32 local cols][US_STR] (k-permuted tf32)
    float* hs = sm + 32 * US_STR;         // [32 batches][US_STR]   (k-permuted tf32)
    float* gp = sm + 64 * US_STR;         // [2 khalf][32 batches][GP_STR] partial preacts

    const int bid = blockIdx.x;
    const int dir = bid & 1;
    const int blk = bid >> 1;             // 0..63
    const int chunk = blk >> 4;           // 0..3 (this CTA's producer chunk)
    const int u0  = blk * 8;
    const int tid = threadIdx.x;
    const int lane = tid & 31, wid = tid >> 5;
    const int gid = lane >> 2, tig = lane & 3;
    const int mhalf = wid & 1;
    const int gpair = (wid >> 1) & 1;
    const int khalf = wid >> 2;           // threads 0-127: 0, 128-255: 1
    const int g0 = gpair * 2, g1 = g0 + 1;
    const int r0 = mhalf * 16 + gid;
    const int lt  = tid & 127;            // index within K-half group
    const int sub = lt >> 6;              // 0/1: sub-group owning one chunk
    const int ltg = lt & 63;              // index within sub-group
    const int ck  = khalf * 2 + sub;      // chunk this sub-group consumes
    const float* __restrict__ Uw = dir ? Ub : Uf;

    // Epoch base: own chunk's word (race-free pre-arrival read; all words equal
    // at every replay start).
    const unsigned ep0 = g_chep[dir][chunk][0];

    // ---- load U slice into smem: Us[localcol][perm8(k)] (tf32), 256 threads ----
    {
        int ci = tid & 31;                // local col: gate(ci>>3) x unit(ci&7)
        int kc = tid >> 5;                // k chunk (0..7), 64 k each
        int g  = ci >> 3, uul = ci & 7;
        const float* src = Uw + (size_t)(g * U_DIM + u0 + uul);
        float* dst = Us + ci * US_STR;
        for (int k = kc * 64; k < kc * 64 + 64; k++)
            dst[perm8(k)] = tf32f(src[(size_t)k * NG]);
    }

    // ---- init state: h0 = c0 = z; h stored k-PERMUTED + tf32-rounded ----
    float cst;
    {
        int b = tid >> 3, uu = tid & 7;
        float zv = z[b * U_DIM + u0 + uu];
        cst = zv;
        g_hbuf[dir][0][b][u0 + ((uu & 3) << 1) + (uu >> 2)] = tf32f(zv);
    }
    __syncthreads();
    if (tid == 0) ch_arrive(dir, chunk, ep0 + 1u);

    const float* hrow0 = hs + r0 * US_STR;
    const float* hrow1 = hs + (r0 + 8) * US_STR;
    const float* urow0 = Us + (g0 * 8 + gid) * US_STR;
    const float* urow1 = Us + (g1 * 8 + gid) * US_STR;
    float* gpb = gp + khalf * 32 * GP_STR;
    const float* xgbase = &g_xg[dir][0][0][0];
    const unsigned hs_s = (unsigned)__cvta_generic_to_shared(hs);
    const int eb = tid >> 3, euu = tid & 7;           // epilogue (batch, unit)
    const int kq = khalf * 256 + sub * 128;           // this sub-group's k-range

    for (int s = 0; s < T_SEQ; s++) {
        const int buf = s & 1;
        const int tt  = dir ? (T_SEQ - 1 - s) : s;

        // prefetch xg for this step (independent of barrier; hides under spin)
        float xr[4];
        {
            const float* xp = xgbase + ((size_t)eb * T_SEQ + tt) * NG + u0 + euu;
            xr[0] = xp[0];
            xr[1] = xp[U_DIM];
            xr[2] = xp[2 * U_DIM];
            xr[3] = xp[3 * U_DIM];
        }

        // parallel per-sub-group: poll own chunk's 16 producers, stage 16 KB
        const float* hsrcBase = &g_hbuf[dir][buf][0][0];
        if (ltg == 0) ch_wait(dir, ck, ep0, 1u + (unsigned)s);
        asm volatile("bar.sync %0, 64;" :: "r"(1 + khalf * 2 + sub));
        #pragma unroll
        for (int j = 0; j < 16; j++) {
            int idx = j * 64 + ltg;               // 0..1023
            int b   = idx >> 5;
            int k   = kq + (idx & 31) * 4;
            const float* src = hsrcBase + b * U_DIM + k;
            unsigned dst = hs_s + (unsigned)(b * US_STR + k) * 4u;
            asm volatile("cp.async.cg.shared.global [%0], [%1], 16;" :: "r"(dst), "l"(src));
        }
        asm volatile("cp.async.commit_group;");
        asm volatile("cp.async.wait_group 0;");
        asm volatile("bar.sync %0, 128;" :: "r"(5 + khalf));   // join both sub-groups

        float c0f[4] = {0, 0, 0, 0}, c1f[4] = {0, 0, 0, 0};

        // straight mma run over this khalf's 256 k (32 kb)
        #pragma unroll 4
        for (int kb = 0; kb < 32; kb++) {
            int o = khalf * 256 + kb * 8 + 2 * tig;
            uint2 ar0 = *(const uint2*)(hrow0 + o);
            uint2 ar1 = *(const uint2*)(hrow1 + o);
            uint2 bu0 = *(const uint2*)(urow0 + o);
            uint2 bu1 = *(const uint2*)(urow1 + o);
            mma8(c0f, ar0.x, ar1.x, ar0.y, ar1.y, bu0.x, bu0.y);
            mma8(c1f, ar0.x, ar1.x, ar0.y, ar1.y, bu1.x, bu1.y);
        }

        // publish partial preactivations
        *(float2*)&gpb[r0 * GP_STR + g0 * 8 + 2 * tig]       = make_float2(c0f[0], c0f[1]);
        *(float2*)&gpb[(r0 + 8) * GP_STR + g0 * 8 + 2 * tig] = make_float2(c0f[2], c0f[3]);
        *(float2*)&gpb[r0 * GP_STR + g1 * 8 + 2 * tig]       = make_float2(c1f[0], c1f[1]);
        *(float2*)&gpb[(r0 + 8) * GP_STR + g1 * 8 + 2 * tig] = make_float2(c1f[2], c1f[3]);
        __syncthreads();

        // epilogue: reduce K-halves + xg, gates (i,f,c,o), update, publish h FIRST
        float hv;
        {
            const float* p0 = gp + eb * GP_STR;
            const float* p1 = gp + (32 + eb) * GP_STR;
            float iv = fsigm(xr[0] + p0[euu]       + p1[euu]);
            float fv = fsigm(xr[1] + p0[8 + euu]   + p1[8 + euu]);
            float cc = ftanh(xr[2] + p0[16 + euu]  + p1[16 + euu]);
            float ov = fsigm(xr[3] + p0[24 + euu]  + p1[24 + euu]);
            cst = fv * cst + iv * cc;
            hv = ov * ftanh(cst);
            g_hbuf[dir][buf ^ 1][eb][u0 + ((euu & 3) << 1) + (euu >> 2)] = tf32f(hv);
        }
        __syncthreads();

        // arrive (release our slice of h(s+1)) BEFORE output stores
        if (tid == 0) ch_arrive(dir, chunk, ep0 + 2u + (unsigned)s);

        if (dir == 0)
            out[((size_t)eb * T_SEQ + s) * U_DIM + u0 + euu] = hv;
        else
            g_hb_out[eb][tt][u0 + euu] = hv;
    }
}

// =================================================================================
// Kernel C: out += backward outputs
// =================================================================================
__global__ void add_bwd(float* __restrict__ out)
{
    int i = blockIdx.x * blockDim.x + threadIdx.x;
    const int n4 = B_DIM * T_SEQ * U_DIM / 4;
    if (i < n4) {
        float4 a = ((float4*)out)[i];
        float4 b = ((const float4*)&g_hb_out[0][0][0])[i];
        a.x += b.x; a.y += b.y; a.z += b.z; a.w += b.w;
        ((float4*)out)[i] = a;
    }
}

// =================================================================================
extern "C" void kernel_launch(void* const* d_in, const int* in_sizes, int n_in,
                              void* d_out, int out_size)
{
    const float* x  = (const float*)d_in[0];
    const float* z  = (const float*)d_in[1];
    const float* Wf = (const float*)d_in[2];
    const float* Uf = (const float*)d_in[3];
    const float* bf = (const float*)d_in[4];
    const float* Wb = (const float*)d_in[5];
    const float* Ub = (const float*)d_in[6];
    const float* bb = (const float*)d_in[7];
    float* out = (float*)d_out;

    cudaFuncSetAttribute(gemm_xg, cudaFuncAttributeMaxDynamicSharedMemorySize, GSMEM);
    cudaFuncSetAttribute(lstm_rec, cudaFuncAttributeMaxDynamicSharedMemorySize, SMEM_REC);

    // pre-passes: tf32-rounded, k-permuted x (in place layout) and transposed W
    {
        int nblk = (M_TOT * D_DIM / 8 + 255) / 256;
        cvt_xP<<<nblk, 256>>>(x);
    }
    cvt_WP<<<dim3(D_DIM / 32, NG / 32, 2), dim3(32, 8)>>>(Wf, Wb);

    dim3 gg(M_TOT / 128, NG / 128, 2);
    gemm_xg<<<gg, 256, GSMEM>>>(bf, bb);
    lstm_rec<<<2 * NCTA_DIR, REC_THREADS, SMEM_REC>>>(z, Uf, Ub, out);
    add_bwd<<<(B_DIM * T_SEQ * U_DIM / 4 + 255) / 256, 256>>>(out);
}